// round 3
// baseline (speedup 1.0000x reference)
#include <cuda_runtime.h>
#include <math.h>

// ---------------- problem constants ----------------
#define DIMX 512
#define D1X  1536
#define BATCH 16
#define HHX 32
#define WWX 32
#define NTOK 1024                 // H*W
#define MTOT (BATCH*NTOK)         // 16384 tokens
#define RPED 64
#define GLUX 1024
#define NPOS 4096                 // (2H)*(2W)

// ---------------- scratch (device globals; no allocation in kernel_launch) ----------------
__device__ float g_T[NPOS * RPED];                    // 1 MB   silu(srms(rpe layer-3 out))
__device__ float g_coef[(size_t)D1X * NPOS];          // 25 MB  coef^T [c][pos] with decay
__device__ float g_u[(size_t)MTOT * D1X];             // 100 MB u (token-major)
__device__ float g_vt[(size_t)D1X * MTOT];            // 100 MB v^T [c][b*1024+pos]
__device__ float g_ot[(size_t)D1X * MTOT];            // 100 MB conv out^T [c][token]
__device__ float g_g[(size_t)MTOT * D1X];             // 100 MB u * out (token-major)
__device__ float g_x1[(size_t)MTOT * DIMX];           // 33 MB  x + gtu
__device__ float g_h1[(size_t)MTOT * GLUX];           // 67 MB  silu(x1@l1+b1)
__device__ float g_h2[(size_t)MTOT * GLUX];           // 67 MB  h1 * (x1@l2+b2)
__device__ float g_mlp[(size_t)MTOT * DIMX];          // 33 MB  mlp pre-norm

__device__ __forceinline__ float silu_f(float x) {
    return x / (1.0f + __expf(-x));
}

// ---------------- RPE position MLP: pos -> silu(srms(layer3 out)), 64-dim ----------------
__global__ __launch_bounds__(64) void rpe_mlp_kernel(
    const float* __restrict__ pos_w, const float* __restrict__ pos_b,
    const float* __restrict__ lw, const float* __restrict__ lb,
    float* __restrict__ T)
{
    __shared__ float sx[64];
    __shared__ float st[64];
    int p = blockIdx.x;
    int tid = threadIdx.x;
    int a = p >> 6, b = p & 63;
    float di = (a < 32) ? (float)a : (float)(a - 64);
    float dj = (b < 32) ? (float)b : (float)(b - 64);

    // x0 = pos @ pos_w + pos_b ; pos_w is (2, 64)
    float x = di * pos_w[tid] + dj * pos_w[64 + tid] + pos_b[tid];

    for (int l = 0; l < 3; l++) {
        sx[tid] = x;
        __syncthreads();
        float ss = 0.f;
        #pragma unroll 8
        for (int k = 0; k < 64; k++) ss += sx[k] * sx[k];
        float rms = sqrtf(ss * (1.0f / 64.0f));
        float t = silu_f(x / (rms + 1e-8f));
        st[tid] = t;
        __syncthreads();
        float y = lb[l * 64 + tid];
        #pragma unroll 8
        for (int k = 0; k < 64; k++) y += st[k] * lw[l * 4096 + k * 64 + tid];
        x = y;
        __syncthreads();
    }
    sx[tid] = x;
    __syncthreads();
    float ss = 0.f;
    #pragma unroll 8
    for (int k = 0; k < 64; k++) ss += sx[k] * sx[k];
    float rms = sqrtf(ss * (1.0f / 64.0f));
    T[p * 64 + tid] = silu_f(x / (rms + 1e-8f));
}

// ---------------- generic fp32 SGEMM, 128x128x16 tile, 8x8 microtile, epilogues ----------------
// epi: 0 = +bias
//      1 = silu(+bias)
//      2 = silu(+bias), transposed store out[col*M + row]
//      3 = extra[row,col] + (+bias)            (residual add)
//      4 = extra[row,col] * (+bias)            (gated GLU branch)
//      5 = decay(row) * (+bias), transposed store (RPE coef)
__global__ __launch_bounds__(256) void sgemm_epi(
    const float* __restrict__ A, const float* __restrict__ Bm,
    const float* __restrict__ bias, const float* __restrict__ extra,
    float* __restrict__ out, int M, int N, int K, int epi)
{
    __shared__ float As[16][128];
    __shared__ float Bs[16][128];
    int tid = threadIdx.x;
    int r0 = blockIdx.y * 128;
    int c0 = blockIdx.x * 128;

    int rowA = tid >> 2;          // 0..63
    int colA = (tid & 3) << 2;    // 0,4,8,12
    int kB   = tid >> 5;          // 0..7
    int cB   = (tid & 31) << 2;   // 0..124
    int ty = tid >> 4, tx = tid & 15;

    float acc[8][8];
    #pragma unroll
    for (int i = 0; i < 8; i++)
        #pragma unroll
        for (int j = 0; j < 8; j++) acc[i][j] = 0.f;

    for (int k0 = 0; k0 < K; k0 += 16) {
        float4 a0 = *(const float4*)(A + (size_t)(r0 + rowA) * K + k0 + colA);
        float4 a1 = *(const float4*)(A + (size_t)(r0 + rowA + 64) * K + k0 + colA);
        As[colA + 0][rowA] = a0.x; As[colA + 1][rowA] = a0.y;
        As[colA + 2][rowA] = a0.z; As[colA + 3][rowA] = a0.w;
        As[colA + 0][rowA + 64] = a1.x; As[colA + 1][rowA + 64] = a1.y;
        As[colA + 2][rowA + 64] = a1.z; As[colA + 3][rowA + 64] = a1.w;
        float4 b0 = *(const float4*)(Bm + (size_t)(k0 + kB) * N + c0 + cB);
        float4 b1 = *(const float4*)(Bm + (size_t)(k0 + kB + 8) * N + c0 + cB);
        *(float4*)&Bs[kB][cB] = b0;
        *(float4*)&Bs[kB + 8][cB] = b1;
        __syncthreads();

        #pragma unroll
        for (int k = 0; k < 16; k++) {
            float4 av0 = *(const float4*)&As[k][ty * 8];
            float4 av1 = *(const float4*)&As[k][ty * 8 + 4];
            float4 bv0 = *(const float4*)&Bs[k][tx * 8];
            float4 bv1 = *(const float4*)&Bs[k][tx * 8 + 4];
            float ar[8] = {av0.x, av0.y, av0.z, av0.w, av1.x, av1.y, av1.z, av1.w};
            float br[8] = {bv0.x, bv0.y, bv0.z, bv0.w, bv1.x, bv1.y, bv1.z, bv1.w};
            #pragma unroll
            for (int i = 0; i < 8; i++)
                #pragma unroll
                for (int j = 0; j < 8; j++)
                    acc[i][j] += ar[i] * br[j];
        }
        __syncthreads();
    }

    #pragma unroll
    for (int i = 0; i < 8; i++) {
        int row = r0 + ty * 8 + i;
        float dec = 1.f;
        if (epi == 5) {
            int a = row >> 6, b = row & 63;
            float adi = (a < 32) ? (float)a : (float)(64 - a);
            float adj = (b < 32) ? (float)b : (float)(64 - b);
            // gamma^(|di|+|dj|), gamma = 0.999 -> ln(gamma) = -1.00050033e-3
            dec = __expf(-1.00050033e-3f * (adi + adj));
        }
        #pragma unroll
        for (int j = 0; j < 8; j++) {
            int col = c0 + tx * 8 + j;
            float val = acc[i][j] + bias[col];
            size_t oidx = (size_t)row * N + col;
            if (epi == 0)       out[oidx] = val;
            else if (epi == 1)  out[oidx] = silu_f(val);
            else if (epi == 2)  out[(size_t)col * M + row] = silu_f(val);
            else if (epi == 3)  out[oidx] = extra[oidx] + val;
            else if (epi == 4)  out[oidx] = extra[oidx] * val;
            else                out[(size_t)col * M + row] = dec * val;
        }
    }
}

// ---------------- Toeplitz token mixing (dense form of the FFT circular conv) ----------------
// out[c][b][i*32+j] = sum_{p,q<32} coef[c][((i-p)&63)*64 + ((j-q)&63)] * v[c][b][p*32+q]
// One block = one channel c x 8 batches. Thread t: positions {t, t+256, t+512, t+768} x 8 batches.
__global__ __launch_bounds__(256) void conv_toeplitz(
    const float* __restrict__ coef, const float* __restrict__ vt, float* __restrict__ ot)
{
    __shared__ float sc[4096];   // 16 KB coef for this channel
    __shared__ float sv[8192];   // 32 KB v for 8 batches
    int c = blockIdx.x;
    int bg = blockIdx.y;         // batch group (0/1) -> batches bg*8..bg*8+7
    int tid = threadIdx.x;

    const float* cp = coef + (size_t)c * 4096;
    const float* vp = vt + (size_t)c * MTOT + (size_t)bg * 8 * 1024;
    for (int i = tid; i < 4096; i += 256) sc[i] = cp[i];
    for (int i = tid; i < 8192; i += 256) sv[i] = vp[i];
    __syncthreads();

    float acc[4][8];
    #pragma unroll
    for (int t = 0; t < 4; t++)
        #pragma unroll
        for (int bb = 0; bb < 8; bb++) acc[t][bb] = 0.f;

    int i0 = tid >> 5;   // base output row 0..7 (positions add +8 per t)
    int j  = tid & 31;   // output col

    for (int p = 0; p < 32; p++) {
        int ro[4];
        #pragma unroll
        for (int t = 0; t < 4; t++) ro[t] = ((i0 + 8 * t - p) & 63) << 6;
        int base = p << 5;
        #pragma unroll 4
        for (int q = 0; q < 32; q++) {
            int co = (j - q) & 63;
            float cf0 = sc[ro[0] + co];
            float cf1 = sc[ro[1] + co];
            float cf2 = sc[ro[2] + co];
            float cf3 = sc[ro[3] + co];
            #pragma unroll
            for (int bb = 0; bb < 8; bb++) {
                float vv = sv[bb * 1024 + base + q];   // broadcast across warp
                acc[0][bb] += cf0 * vv;
                acc[1][bb] += cf1 * vv;
                acc[2][bb] += cf2 * vv;
                acc[3][bb] += cf3 * vv;
            }
        }
    }

    float* op = ot + (size_t)c * MTOT + (size_t)bg * 8 * 1024;
    #pragma unroll
    for (int t = 0; t < 4; t++)
        #pragma unroll
        for (int bb = 0; bb < 8; bb++)
            op[bb * 1024 + t * 256 + tid] = acc[t][bb];
}

// ---------------- gate: g[token][c] = u[token][c] * ot[c][token] (tiled transpose) ----------------
__global__ void gate_mul(const float* __restrict__ u, const float* __restrict__ ot,
                         float* __restrict__ g)
{
    __shared__ float sm[32][33];
    int c0 = blockIdx.x * 32;
    int r0 = blockIdx.y * 32;
    int tx = threadIdx.x, ty = threadIdx.y;
    sm[ty][tx] = ot[(size_t)(c0 + ty) * MTOT + r0 + tx];
    __syncthreads();
    size_t idx = (size_t)(r0 + ty) * D1X + c0 + tx;
    g[idx] = u[idx] * sm[tx][ty];
}

// ---------------- final: out = x1 + srms(mlp) rowwise over 512 ----------------
__global__ __launch_bounds__(128) void final_srms(
    const float* __restrict__ x1, const float* __restrict__ mlp, float* __restrict__ out)
{
    __shared__ float sred[4];
    int row = blockIdx.x;
    int tid = threadIdx.x;
    const float* mp = mlp + (size_t)row * DIMX;
    float v[4];
    float ss = 0.f;
    #pragma unroll
    for (int t = 0; t < 4; t++) { v[t] = mp[tid + t * 128]; ss += v[t] * v[t]; }
    #pragma unroll
    for (int o = 16; o > 0; o >>= 1) ss += __shfl_xor_sync(0xffffffffu, ss, o);
    if ((tid & 31) == 0) sred[tid >> 5] = ss;
    __syncthreads();
    float tot = sred[0] + sred[1] + sred[2] + sred[3];
    float rms = sqrtf(tot * (1.0f / 512.0f));
    float inv = 1.0f / (rms + 1e-8f);
    const float* xp = x1 + (size_t)row * DIMX;
    float* op = out + (size_t)row * DIMX;
    #pragma unroll
    for (int t = 0; t < 4; t++) op[tid + t * 128] = xp[tid + t * 128] + v[t] * inv;
}

// ---------------- driver ----------------
extern "C" void kernel_launch(void* const* d_in, const int* in_sizes, int n_in,
                              void* d_out, int out_size)
{
    (void)in_sizes; (void)n_in; (void)out_size;
    const float* x      = (const float*)d_in[0];
    const float* u_w    = (const float*)d_in[1];
    const float* u_b    = (const float*)d_in[2];
    const float* v_w    = (const float*)d_in[3];
    const float* v_b    = (const float*)d_in[4];
    const float* o_w    = (const float*)d_in[5];
    const float* o_b    = (const float*)d_in[6];
    const float* pos_w  = (const float*)d_in[7];
    const float* pos_b  = (const float*)d_in[8];
    const float* rpe_lw = (const float*)d_in[9];
    const float* rpe_lb = (const float*)d_in[10];
    const float* rpe_ow = (const float*)d_in[11];
    const float* rpe_ob = (const float*)d_in[12];
    const float* l1_w   = (const float*)d_in[13];
    const float* l1_b   = (const float*)d_in[14];
    const float* l2_w   = (const float*)d_in[15];
    const float* l2_b   = (const float*)d_in[16];
    const float* l3_w   = (const float*)d_in[17];
    const float* l3_b   = (const float*)d_in[18];
    float* out = (float*)d_out;

    float *T, *coef, *u, *vt, *ot, *g, *x1, *h1, *h2, *mlp;
    cudaGetSymbolAddress((void**)&T,    g_T);
    cudaGetSymbolAddress((void**)&coef, g_coef);
    cudaGetSymbolAddress((void**)&u,    g_u);
    cudaGetSymbolAddress((void**)&vt,   g_vt);
    cudaGetSymbolAddress((void**)&ot,   g_ot);
    cudaGetSymbolAddress((void**)&g,    g_g);
    cudaGetSymbolAddress((void**)&x1,   g_x1);
    cudaGetSymbolAddress((void**)&h1,   g_h1);
    cudaGetSymbolAddress((void**)&h2,   g_h2);
    cudaGetSymbolAddress((void**)&mlp,  g_mlp);

    // RPE MLP trunk + coef projection (with decay, transposed store)
    rpe_mlp_kernel<<<NPOS, 64>>>(pos_w, pos_b, rpe_lw, rpe_lb, T);
    sgemm_epi<<<dim3(D1X / 128, NPOS / 128), 256>>>(T, rpe_ow, rpe_ob, nullptr, coef,
                                                    NPOS, D1X, RPED, 5);
    // u, v projections
    sgemm_epi<<<dim3(D1X / 128, MTOT / 128), 256>>>(x, u_w, u_b, nullptr, u,
                                                    MTOT, D1X, DIMX, 1);
    sgemm_epi<<<dim3(D1X / 128, MTOT / 128), 256>>>(x, v_w, v_b, nullptr, vt,
                                                    MTOT, D1X, DIMX, 2);
    // token mixing (dense Toeplitz form of the FFT circular conv)
    conv_toeplitz<<<dim3(D1X, 2), 256>>>(coef, vt, ot);
    // gate + output projection + residual
    gate_mul<<<dim3(D1X / 32, MTOT / 32), dim3(32, 32)>>>(u, ot, g);
    sgemm_epi<<<dim3(DIMX / 128, MTOT / 128), 256>>>(g, o_w, o_b, x, x1,
                                                     MTOT, DIMX, D1X, 3);
    // GLU MLP
    sgemm_epi<<<dim3(GLUX / 128, MTOT / 128), 256>>>(x1, l1_w, l1_b, nullptr, h1,
                                                     MTOT, GLUX, DIMX, 1);
    sgemm_epi<<<dim3(GLUX / 128, MTOT / 128), 256>>>(x1, l2_w, l2_b, h1, h2,
                                                     MTOT, GLUX, DIMX, 4);
    sgemm_epi<<<dim3(DIMX / 128, MTOT / 128), 256>>>(h2, l3_w, l3_b, nullptr, mlp,
                                                     MTOT, DIMX, GLUX, 0);
    // out = x1 + srms(mlp)
    final_srms<<<MTOT, 128>>>(x1, mlp, out);
}

// round 6
// speedup vs baseline: 1.6832x; 1.6832x over previous
#include <cuda_runtime.h>
#include <cuda_bf16.h>
#include <math.h>
#include <stdint.h>

#define DIMX 512
#define D1X  1536
#define BATCH 16
#define NTOK 1024
#define MTOT (BATCH*NTOK)
#define RPED 64
#define GLUX 1024
#define NPOS 4096

__device__ float g_T[NPOS * RPED];
__device__ float g_coef[(size_t)D1X * NPOS];
__device__ float g_u[(size_t)MTOT * D1X];
__device__ float g_vt[(size_t)D1X * MTOT];
__device__ float g_ot[(size_t)D1X * MTOT];
__device__ float g_g[(size_t)MTOT * D1X];
__device__ float g_x1[(size_t)MTOT * DIMX];
__device__ float g_h1[(size_t)MTOT * GLUX];
__device__ float g_h2[(size_t)MTOT * GLUX];
__device__ float g_mlp[(size_t)MTOT * DIMX];

__device__ __forceinline__ float silu_f(float x) { return x / (1.0f + __expf(-x)); }

__device__ __forceinline__ uint32_t smem_u32(const void* p) {
    uint32_t a;
    asm("{ .reg .u64 t; cvta.to.shared.u64 t, %1; cvt.u32.u64 %0, t; }" : "=r"(a) : "l"(p));
    return a;
}

__device__ __forceinline__ void ldsm4(uint32_t* r, uint32_t addr) {
    asm volatile("ldmatrix.sync.aligned.m8n8.x4.shared.b16 {%0,%1,%2,%3}, [%4];"
                 : "=r"(r[0]), "=r"(r[1]), "=r"(r[2]), "=r"(r[3]) : "r"(addr));
}
__device__ __forceinline__ void ldsm4t(uint32_t* r, uint32_t addr) {
    asm volatile("ldmatrix.sync.aligned.m8n8.x4.trans.shared.b16 {%0,%1,%2,%3}, [%4];"
                 : "=r"(r[0]), "=r"(r[1]), "=r"(r[2]), "=r"(r[3]) : "r"(addr));
}
__device__ __forceinline__ void mma16816(float* d, const uint32_t* a, const uint32_t* b) {
    asm volatile(
        "mma.sync.aligned.m16n8k16.row.col.f32.bf16.bf16.f32 "
        "{%0,%1,%2,%3}, {%4,%5,%6,%7}, {%8,%9}, {%0,%1,%2,%3};"
        : "+f"(d[0]), "+f"(d[1]), "+f"(d[2]), "+f"(d[3])
        : "r"(a[0]), "r"(a[1]), "r"(a[2]), "r"(a[3]), "r"(b[0]), "r"(b[1]));
}

__device__ __forceinline__ uint32_t pk_bf16(float a, float b) {
    __nv_bfloat162 t = __floats2bfloat162_rn(a, b);
    return *reinterpret_cast<uint32_t*>(&t);
}
__device__ __forceinline__ void split8(const float* f, uint4& h4, uint4& l4) {
    float lf[8];
#pragma unroll
    for (int i = 0; i < 8; i++) {
        float hv = __bfloat162float(__float2bfloat16(f[i]));
        lf[i] = f[i] - hv;
    }
    h4.x = pk_bf16(f[0], f[1]); h4.y = pk_bf16(f[2], f[3]);
    h4.z = pk_bf16(f[4], f[5]); h4.w = pk_bf16(f[6], f[7]);
    l4.x = pk_bf16(lf[0], lf[1]); l4.y = pk_bf16(lf[2], lf[3]);
    l4.z = pk_bf16(lf[4], lf[5]); l4.w = pk_bf16(lf[6], lf[7]);
}

// ---- split-bf16 mma.sync GEMM: out[M,N] = A[M,K] @ W[K,N] + bias ----
// epi: 0 = +bias ; 1 = silu ; 2 = silu transposed out[n*M+m] ; 3 = decay(m)* transposed
// CTA 128x128, 8 warps (4 along M x 2 along N), warp tile 32x64, K sliced by 32.
// smem: A [2 ksteps][128 rows][24 halves] (row stride 48B, conflict-free ldmatrix)
//       B [2 ksteps][16 rows][136 halves] (row stride 272B, conflict-free ldmatrix.trans)
#define S_AH 0
#define S_AL 12288
#define S_BH 24576
#define S_BL 33280
#define S_TOT 41984

__global__ __launch_bounds__(256, 1) void mma_gemm(
    const float* __restrict__ A, const float* __restrict__ W,
    const float* __restrict__ bias, float* __restrict__ out,
    int M, int N, int K, int epi)
{
    __shared__ char smem[S_TOT];
    uint32_t sbase = smem_u32(smem);
    int tid = threadIdx.x;
    int wid = tid >> 5, lid = tid & 31;
    int wm = wid & 3, wn = wid >> 2;
    int m0 = blockIdx.y * 128, n0 = blockIdx.x * 128;

    float acc[2][8][4];
#pragma unroll
    for (int mt = 0; mt < 2; mt++)
#pragma unroll
        for (int nt = 0; nt < 8; nt++)
#pragma unroll
            for (int c = 0; c < 4; c++) acc[mt][nt][c] = 0.f;

    const int arow = tid >> 1;          // 0..127
    const int aks  = tid & 1;           // kstep of this thread's A chunk
    const int brow = tid >> 3;          // 0..31 (k row within 32-slice)
    const int bcol = (tid & 7) * 16;    // n offset within 128

    float4 ra[4], rb[4];
    const int S = K >> 5;

    // ---- prologue: slice 0 ----
    {
        const float* p = A + (size_t)(m0 + arow) * K + aks * 16;
        ra[0] = ((const float4*)p)[0]; ra[1] = ((const float4*)p)[1];
        ra[2] = ((const float4*)p)[2]; ra[3] = ((const float4*)p)[3];
        const float* q = W + (size_t)brow * N + n0 + bcol;
        rb[0] = ((const float4*)q)[0]; rb[1] = ((const float4*)q)[1];
        rb[2] = ((const float4*)q)[2]; rb[3] = ((const float4*)q)[3];
    }
    // store slice 0
    {
        float f[8]; uint4 h4, l4;
        f[0]=ra[0].x; f[1]=ra[0].y; f[2]=ra[0].z; f[3]=ra[0].w;
        f[4]=ra[1].x; f[5]=ra[1].y; f[6]=ra[1].z; f[7]=ra[1].w;
        split8(f, h4, l4);
        *(uint4*)(smem + S_AH + aks*6144 + arow*48)      = h4;
        *(uint4*)(smem + S_AL + aks*6144 + arow*48)      = l4;
        f[0]=ra[2].x; f[1]=ra[2].y; f[2]=ra[2].z; f[3]=ra[2].w;
        f[4]=ra[3].x; f[5]=ra[3].y; f[6]=ra[3].z; f[7]=ra[3].w;
        split8(f, h4, l4);
        *(uint4*)(smem + S_AH + aks*6144 + arow*48 + 16) = h4;
        *(uint4*)(smem + S_AL + aks*6144 + arow*48 + 16) = l4;
        int bks = brow >> 4, br = brow & 15;
        f[0]=rb[0].x; f[1]=rb[0].y; f[2]=rb[0].z; f[3]=rb[0].w;
        f[4]=rb[1].x; f[5]=rb[1].y; f[6]=rb[1].z; f[7]=rb[1].w;
        split8(f, h4, l4);
        *(uint4*)(smem + S_BH + bks*4352 + br*272 + bcol*2)      = h4;
        *(uint4*)(smem + S_BL + bks*4352 + br*272 + bcol*2)      = l4;
        f[0]=rb[2].x; f[1]=rb[2].y; f[2]=rb[2].z; f[3]=rb[2].w;
        f[4]=rb[3].x; f[5]=rb[3].y; f[6]=rb[3].z; f[7]=rb[3].w;
        split8(f, h4, l4);
        *(uint4*)(smem + S_BH + bks*4352 + br*272 + bcol*2 + 16) = h4;
        *(uint4*)(smem + S_BL + bks*4352 + br*272 + bcol*2 + 16) = l4;
    }
    __syncthreads();

    const int lr = lid & 7, q1 = (lid >> 3) & 1, q2 = lid >> 4;

    for (int s = 0; s < S; s++) {
        if (s + 1 < S) {
            const float* p = A + (size_t)(m0 + arow) * K + (s + 1) * 32 + aks * 16;
            ra[0] = ((const float4*)p)[0]; ra[1] = ((const float4*)p)[1];
            ra[2] = ((const float4*)p)[2]; ra[3] = ((const float4*)p)[3];
            const float* q = W + (size_t)((s + 1) * 32 + brow) * N + n0 + bcol;
            rb[0] = ((const float4*)q)[0]; rb[1] = ((const float4*)q)[1];
            rb[2] = ((const float4*)q)[2]; rb[3] = ((const float4*)q)[3];
        }
        // ---- compute both ksteps of this slice ----
#pragma unroll
        for (int ks = 0; ks < 2; ks++) {
            uint32_t ah[2][4], al[2][4];
#pragma unroll
            for (int mt = 0; mt < 2; mt++) {
                int mrow = wm * 32 + mt * 16 + lr + q1 * 8;
                uint32_t aoff = sbase + S_AH + ks * 6144 + mrow * 48 + q2 * 16;
                ldsm4(ah[mt], aoff);
                ldsm4(al[mt], aoff + (S_AL - S_AH));
            }
#pragma unroll
            for (int nt = 0; nt < 4; nt++) {
                int nb = wn * 64 + nt * 16;
                uint32_t boff = sbase + S_BH + ks * 4352 + (lr + q1 * 8) * 272
                              + (nb + q2 * 8) * 2;
                uint32_t bh[4], bl[4];
                ldsm4t(bh, boff);
                ldsm4t(bl, boff + (S_BL - S_BH));
#pragma unroll
                for (int mt = 0; mt < 2; mt++) {
                    mma16816(acc[mt][nt * 2 + 0], ah[mt], bh);
                    mma16816(acc[mt][nt * 2 + 0], ah[mt], bl);
                    mma16816(acc[mt][nt * 2 + 0], al[mt], bh);
                    mma16816(acc[mt][nt * 2 + 1], ah[mt], bh + 2);
                    mma16816(acc[mt][nt * 2 + 1], ah[mt], bl + 2);
                    mma16816(acc[mt][nt * 2 + 1], al[mt], bh + 2);
                }
            }
        }
        __syncthreads();
        if (s + 1 < S) {
            float f[8]; uint4 h4, l4;
            f[0]=ra[0].x; f[1]=ra[0].y; f[2]=ra[0].z; f[3]=ra[0].w;
            f[4]=ra[1].x; f[5]=ra[1].y; f[6]=ra[1].z; f[7]=ra[1].w;
            split8(f, h4, l4);
            *(uint4*)(smem + S_AH + aks*6144 + arow*48)      = h4;
            *(uint4*)(smem + S_AL + aks*6144 + arow*48)      = l4;
            f[0]=ra[2].x; f[1]=ra[2].y; f[2]=ra[2].z; f[3]=ra[2].w;
            f[4]=ra[3].x; f[5]=ra[3].y; f[6]=ra[3].z; f[7]=ra[3].w;
            split8(f, h4, l4);
            *(uint4*)(smem + S_AH + aks*6144 + arow*48 + 16) = h4;
            *(uint4*)(smem + S_AL + aks*6144 + arow*48 + 16) = l4;
            int bks = brow >> 4, br = brow & 15;
            f[0]=rb[0].x; f[1]=rb[0].y; f[2]=rb[0].z; f[3]=rb[0].w;
            f[4]=rb[1].x; f[5]=rb[1].y; f[6]=rb[1].z; f[7]=rb[1].w;
            split8(f, h4, l4);
            *(uint4*)(smem + S_BH + bks*4352 + br*272 + bcol*2)      = h4;
            *(uint4*)(smem + S_BL + bks*4352 + br*272 + bcol*2)      = l4;
            f[0]=rb[2].x; f[1]=rb[2].y; f[2]=rb[2].z; f[3]=rb[2].w;
            f[4]=rb[3].x; f[5]=rb[3].y; f[6]=rb[3].z; f[7]=rb[3].w;
            split8(f, h4, l4);
            *(uint4*)(smem + S_BH + bks*4352 + br*272 + bcol*2 + 16) = h4;
            *(uint4*)(smem + S_BL + bks*4352 + br*272 + bcol*2 + 16) = l4;
            __syncthreads();
        }
    }

    // ---- epilogue ----
    int g = lid >> 2, tg = lid & 3;
#pragma unroll
    for (int mt = 0; mt < 2; mt++) {
        int r0 = m0 + wm * 32 + mt * 16 + g;
        int r1 = r0 + 8;
        float dec0 = 1.f, dec1 = 1.f;
        if (epi == 3) {
            int a = r0 >> 6, b = r0 & 63;
            float adi = (a < 32) ? (float)a : (float)(64 - a);
            float adj = (b < 32) ? (float)b : (float)(64 - b);
            dec0 = __expf(-1.00050033e-3f * (adi + adj));
            a = r1 >> 6; b = r1 & 63;
            adi = (a < 32) ? (float)a : (float)(64 - a);
            adj = (b < 32) ? (float)b : (float)(64 - b);
            dec1 = __expf(-1.00050033e-3f * (adi + adj));
        }
#pragma unroll
        for (int nt = 0; nt < 8; nt++) {
            int col = n0 + wn * 64 + nt * 8 + tg * 2;
            float b0 = bias[col], b1 = bias[col + 1];
            float v00 = acc[mt][nt][0] + b0, v01 = acc[mt][nt][1] + b1;
            float v10 = acc[mt][nt][2] + b0, v11 = acc[mt][nt][3] + b1;
            if (epi == 0) {
                *(float2*)(out + (size_t)r0 * N + col) = make_float2(v00, v01);
                *(float2*)(out + (size_t)r1 * N + col) = make_float2(v10, v11);
            } else if (epi == 1) {
                *(float2*)(out + (size_t)r0 * N + col) = make_float2(silu_f(v00), silu_f(v01));
                *(float2*)(out + (size_t)r1 * N + col) = make_float2(silu_f(v10), silu_f(v11));
            } else if (epi == 2) {
                out[(size_t)col * M + r0]       = silu_f(v00);
                out[(size_t)(col + 1) * M + r0] = silu_f(v01);
                out[(size_t)col * M + r1]       = silu_f(v10);
                out[(size_t)(col + 1) * M + r1] = silu_f(v11);
            } else {
                out[(size_t)col * M + r0]       = dec0 * v00;
                out[(size_t)(col + 1) * M + r0] = dec0 * v01;
                out[(size_t)col * M + r1]       = dec1 * v10;
                out[(size_t)(col + 1) * M + r1] = dec1 * v11;
            }
        }
    }
}

// ---- RPE position MLP ----
__global__ __launch_bounds__(64) void rpe_mlp_kernel(
    const float* __restrict__ pos_w, const float* __restrict__ pos_b,
    const float* __restrict__ lw, const float* __restrict__ lb,
    float* __restrict__ T)
{
    __shared__ float sx[64];
    __shared__ float st[64];
    int p = blockIdx.x;
    int tid = threadIdx.x;
    int a = p >> 6, b = p & 63;
    float di = (a < 32) ? (float)a : (float)(a - 64);
    float dj = (b < 32) ? (float)b : (float)(b - 64);
    float x = di * pos_w[tid] + dj * pos_w[64 + tid] + pos_b[tid];

    for (int l = 0; l < 3; l++) {
        sx[tid] = x;
        __syncthreads();
        float ss = 0.f;
#pragma unroll 8
        for (int k = 0; k < 64; k++) ss += sx[k] * sx[k];
        float rms = sqrtf(ss * (1.0f / 64.0f));
        float t = silu_f(x / (rms + 1e-8f));
        st[tid] = t;
        __syncthreads();
        float y = lb[l * 64 + tid];
#pragma unroll 8
        for (int k = 0; k < 64; k++) y += st[k] * lw[l * 4096 + k * 64 + tid];
        x = y;
        __syncthreads();
    }
    sx[tid] = x;
    __syncthreads();
    float ss = 0.f;
#pragma unroll 8
    for (int k = 0; k < 64; k++) ss += sx[k] * sx[k];
    float rms = sqrtf(ss * (1.0f / 64.0f));
    T[p * 64 + tid] = silu_f(x / (rms + 1e-8f));
}

// ---- Toeplitz token mixing ----
__global__ __launch_bounds__(256) void conv_toeplitz(
    const float* __restrict__ coef, const float* __restrict__ vt, float* __restrict__ ot)
{
    __shared__ float sc[4096];
    __shared__ float sv[8192];
    int c = blockIdx.x;
    int bg = blockIdx.y;
    int tid = threadIdx.x;

    const float* cp = coef + (size_t)c * 4096;
    const float* vp = vt + (size_t)c * MTOT + (size_t)bg * 8 * 1024;
    for (int i = tid; i < 4096; i += 256) sc[i] = cp[i];
    for (int i = tid; i < 8192; i += 256) sv[i] = vp[i];
    __syncthreads();

    float acc[4][8];
#pragma unroll
    for (int t = 0; t < 4; t++)
#pragma unroll
        for (int bb = 0; bb < 8; bb++) acc[t][bb] = 0.f;

    int i0 = tid >> 5;
    int j = tid & 31;

    for (int p = 0; p < 32; p++) {
        int ro[4];
#pragma unroll
        for (int t = 0; t < 4; t++) ro[t] = ((i0 + 8 * t - p) & 63) << 6;
        int base = p << 5;
#pragma unroll 4
        for (int q = 0; q < 32; q++) {
            int co = (j - q) & 63;
            float cf0 = sc[ro[0] + co];
            float cf1 = sc[ro[1] + co];
            float cf2 = sc[ro[2] + co];
            float cf3 = sc[ro[3] + co];
#pragma unroll
            for (int bb = 0; bb < 8; bb++) {
                float vv = sv[bb * 1024 + base + q];
                acc[0][bb] += cf0 * vv;
                acc[1][bb] += cf1 * vv;
                acc[2][bb] += cf2 * vv;
                acc[3][bb] += cf3 * vv;
            }
        }
    }

    float* op = ot + (size_t)c * MTOT + (size_t)bg * 8 * 1024;
#pragma unroll
    for (int t = 0; t < 4; t++)
#pragma unroll
        for (int bb = 0; bb < 8; bb++)
            op[bb * 1024 + t * 256 + tid] = acc[t][bb];
}

// ---- gate: g[token][c] = u[token][c] * ot[c][token] ----
__global__ void gate_mul(const float* __restrict__ u, const float* __restrict__ ot,
                         float* __restrict__ g)
{
    __shared__ float sm[32][33];
    int c0 = blockIdx.x * 32;
    int r0 = blockIdx.y * 32;
    int tx = threadIdx.x, ty = threadIdx.y;
    sm[ty][tx] = ot[(size_t)(c0 + ty) * MTOT + r0 + tx];
    __syncthreads();
    size_t idx = (size_t)(r0 + ty) * D1X + c0 + tx;
    g[idx] = u[idx] * sm[tx][ty];
}

__global__ void ew_add(const float* __restrict__ a, const float* __restrict__ b,
                       float* __restrict__ o, int n4)
{
    int i = blockIdx.x * blockDim.x + threadIdx.x;
    if (i < n4) {
        float4 x = ((const float4*)a)[i];
        float4 y = ((const float4*)b)[i];
        x.x += y.x; x.y += y.y; x.z += y.z; x.w += y.w;
        ((float4*)o)[i] = x;
    }
}

__global__ void ew_mul(const float* __restrict__ a, float* __restrict__ o, int n4)
{
    int i = blockIdx.x * blockDim.x + threadIdx.x;
    if (i < n4) {
        float4 x = ((const float4*)a)[i];
        float4 y = ((float4*)o)[i];
        y.x *= x.x; y.y *= x.y; y.z *= x.z; y.w *= x.w;
        ((float4*)o)[i] = y;
    }
}

__global__ __launch_bounds__(128) void final_srms(
    const float* __restrict__ x1, const float* __restrict__ mlp, float* __restrict__ out)
{
    __shared__ float sred[4];
    int row = blockIdx.x;
    int tid = threadIdx.x;
    const float* mp = mlp + (size_t)row * DIMX;
    float v[4];
    float ss = 0.f;
#pragma unroll
    for (int t = 0; t < 4; t++) { v[t] = mp[tid + t * 128]; ss += v[t] * v[t]; }
#pragma unroll
    for (int o = 16; o > 0; o >>= 1) ss += __shfl_xor_sync(0xffffffffu, ss, o);
    if ((tid & 31) == 0) sred[tid >> 5] = ss;
    __syncthreads();
    float tot = sred[0] + sred[1] + sred[2] + sred[3];
    float rms = sqrtf(tot * (1.0f / 512.0f));
    float inv = 1.0f / (rms + 1e-8f);
    const float* xp = x1 + (size_t)row * DIMX;
    float* op = out + (size_t)row * DIMX;
#pragma unroll
    for (int t = 0; t < 4; t++) op[tid + t * 128] = xp[tid + t * 128] + v[t] * inv;
}

extern "C" void kernel_launch(void* const* d_in, const int* in_sizes, int n_in,
                              void* d_out, int out_size)
{
    (void)in_sizes; (void)n_in; (void)out_size;
    const float* x      = (const float*)d_in[0];
    const float* u_w    = (const float*)d_in[1];
    const float* u_b    = (const float*)d_in[2];
    const float* v_w    = (const float*)d_in[3];
    const float* v_b    = (const float*)d_in[4];
    const float* o_w    = (const float*)d_in[5];
    const float* o_b    = (const float*)d_in[6];
    const float* pos_w  = (const float*)d_in[7];
    const float* pos_b  = (const float*)d_in[8];
    const float* rpe_lw = (const float*)d_in[9];
    const float* rpe_lb = (const float*)d_in[10];
    const float* rpe_ow = (const float*)d_in[11];
    const float* rpe_ob = (const float*)d_in[12];
    const float* l1_w   = (const float*)d_in[13];
    const float* l1_b   = (const float*)d_in[14];
    const float* l2_w   = (const float*)d_in[15];
    const float* l2_b   = (const float*)d_in[16];
    const float* l3_w   = (const float*)d_in[17];
    const float* l3_b   = (const float*)d_in[18];
    float* out = (float*)d_out;

    float *T, *coef, *u, *vt, *ot, *g, *x1, *h1, *h2, *mlp;
    cudaGetSymbolAddress((void**)&T,    g_T);
    cudaGetSymbolAddress((void**)&coef, g_coef);
    cudaGetSymbolAddress((void**)&u,    g_u);
    cudaGetSymbolAddress((void**)&vt,   g_vt);
    cudaGetSymbolAddress((void**)&ot,   g_ot);
    cudaGetSymbolAddress((void**)&g,    g_g);
    cudaGetSymbolAddress((void**)&x1,   g_x1);
    cudaGetSymbolAddress((void**)&h1,   g_h1);
    cudaGetSymbolAddress((void**)&h2,   g_h2);
    cudaGetSymbolAddress((void**)&mlp,  g_mlp);

    rpe_mlp_kernel<<<NPOS, 64>>>(pos_w, pos_b, rpe_lw, rpe_lb, T);
    // coef = decay * (T @ rpe_ow + rpe_ob), transposed store
    mma_gemm<<<dim3(D1X/128, NPOS/128), 256>>>(T, rpe_ow, rpe_ob, coef,
                                               NPOS, D1X, RPED, 3);
    // u = silu(x @ u_w + u_b); vt = silu(x @ v_w + v_b)^T
    mma_gemm<<<dim3(D1X/128, MTOT/128), 256>>>(x, u_w, u_b, u,
                                               MTOT, D1X, DIMX, 1);
    mma_gemm<<<dim3(D1X/128, MTOT/128), 256>>>(x, v_w, v_b, vt,
                                               MTOT, D1X, DIMX, 2);
    conv_toeplitz<<<dim3(D1X, 2), 256>>>(coef, vt, ot);
    gate_mul<<<dim3(D1X/32, MTOT/32), dim3(32, 32)>>>(u, ot, g);
    // x1 = x + (g @ o_w + o_b)
    mma_gemm<<<dim3(DIMX/128, MTOT/128), 256>>>(g, o_w, o_b, mlp,
                                                MTOT, DIMX, D1X, 0);
    ew_add<<<(MTOT*DIMX/4 + 255)/256, 256>>>(x, mlp, x1, MTOT*DIMX/4);
    // GLU MLP
    mma_gemm<<<dim3(GLUX/128, MTOT/128), 256>>>(x1, l1_w, l1_b, h1,
                                                MTOT, GLUX, DIMX, 1);
    mma_gemm<<<dim3(GLUX/128, MTOT/128), 256>>>(x1, l2_w, l2_b, h2,
                                                MTOT, GLUX, DIMX, 0);
    ew_mul<<<(MTOT*GLUX/4 + 255)/256, 256>>>(h1, h2, MTOT*GLUX/4);
    mma_gemm<<<dim3(DIMX/128, MTOT/128), 256>>>(h2, l3_w, l3_b, mlp,
                                                MTOT, DIMX, GLUX, 0);
    final_srms<<<MTOT, 128>>>(x1, mlp, out);
}

// round 12
// speedup vs baseline: 1.8433x; 1.0951x over previous
#include <cuda_runtime.h>
#include <cuda_bf16.h>
#include <math.h>
#include <stdint.h>

#define DIMX 512
#define D1X  1536
#define BATCH 16
#define NTOK 1024
#define MTOT (BATCH*NTOK)
#define RPED 64
#define GLUX 1024
#define NPOS 4096

// fp32 scratch
__device__ float g_T[NPOS * RPED];
__device__ float g_coef[(size_t)D1X * NPOS];
__device__ float g_u[(size_t)MTOT * D1X];
__device__ float g_vt[(size_t)D1X * MTOT];
__device__ float g_ot[(size_t)D1X * MTOT];
__device__ float g_x1[(size_t)MTOT * DIMX];
__device__ float g_h1[(size_t)MTOT * GLUX];
__device__ float g_h2[(size_t)MTOT * GLUX];
__device__ float g_mlp[(size_t)MTOT * DIMX];

// split-bf16 scratch (hi/lo)
__device__ __nv_bfloat16 b_xh[(size_t)MTOT*DIMX],  b_xl[(size_t)MTOT*DIMX];
__device__ __nv_bfloat16 b_Th[NPOS*RPED],          b_Tl[NPOS*RPED];
__device__ __nv_bfloat16 b_uwh[DIMX*D1X],          b_uwl[DIMX*D1X];
__device__ __nv_bfloat16 b_vwh[DIMX*D1X],          b_vwl[DIMX*D1X];
__device__ __nv_bfloat16 b_owh[D1X*DIMX],          b_owl[D1X*DIMX];
__device__ __nv_bfloat16 b_l1h[DIMX*GLUX],         b_l1l[DIMX*GLUX];
__device__ __nv_bfloat16 b_l2h[DIMX*GLUX],         b_l2l[DIMX*GLUX];
__device__ __nv_bfloat16 b_l3h[GLUX*DIMX],         b_l3l[GLUX*DIMX];
__device__ __nv_bfloat16 b_rwh[RPED*D1X],          b_rwl[RPED*D1X];
__device__ __nv_bfloat16 b_gh[(size_t)MTOT*D1X],   b_gl[(size_t)MTOT*D1X];
__device__ __nv_bfloat16 b_x1h[(size_t)MTOT*DIMX], b_x1l[(size_t)MTOT*DIMX];
__device__ __nv_bfloat16 b_h2h[(size_t)MTOT*GLUX], b_h2l[(size_t)MTOT*GLUX];

__device__ __forceinline__ float silu_f(float x) { return x / (1.0f + __expf(-x)); }

__device__ __forceinline__ uint32_t smem_u32(const void* p) {
    uint32_t a;
    asm("{ .reg .u64 t; cvta.to.shared.u64 t, %1; cvt.u32.u64 %0, t; }" : "=r"(a) : "l"(p));
    return a;
}
__device__ __forceinline__ void ldsm4(uint32_t* r, uint32_t addr) {
    asm volatile("ldmatrix.sync.aligned.m8n8.x4.shared.b16 {%0,%1,%2,%3}, [%4];"
                 : "=r"(r[0]), "=r"(r[1]), "=r"(r[2]), "=r"(r[3]) : "r"(addr));
}
__device__ __forceinline__ void ldsm4t(uint32_t* r, uint32_t addr) {
    asm volatile("ldmatrix.sync.aligned.m8n8.x4.trans.shared.b16 {%0,%1,%2,%3}, [%4];"
                 : "=r"(r[0]), "=r"(r[1]), "=r"(r[2]), "=r"(r[3]) : "r"(addr));
}
__device__ __forceinline__ void mma16816(float* d, const uint32_t* a, const uint32_t* b) {
    asm volatile(
        "mma.sync.aligned.m16n8k16.row.col.f32.bf16.bf16.f32 "
        "{%0,%1,%2,%3}, {%4,%5,%6,%7}, {%8,%9}, {%0,%1,%2,%3};"
        : "+f"(d[0]), "+f"(d[1]), "+f"(d[2]), "+f"(d[3])
        : "r"(a[0]), "r"(a[1]), "r"(a[2]), "r"(a[3]), "r"(b[0]), "r"(b[1]));
}
#define CP16(saddr, gptr) \
    asm volatile("cp.async.cg.shared.global [%0], [%1], 16;" :: "r"(saddr), "l"(gptr))
#define CP_COMMIT() asm volatile("cp.async.commit_group;" ::: "memory")
#define CP_WAIT1()  asm volatile("cp.async.wait_group 1;" ::: "memory")

// ---- split-bf16 mma.sync GEMM with cp.async double buffering ----
// A: hi/lo bf16 [M,K]; W: hi/lo bf16 [K,N].  out fp32.
// epi: 0=+bias; 1=silu; 2=silu transposed out[n*M+m]; 3=decay(m)* transposed
// smem per buffer: A[2ks][128][24h] hi(12288)+lo(12288); B[2ks][16][136h] hi(8704)+lo(8704)
#define BUFB 41984
#define OFF_BH 24576

__global__ __launch_bounds__(256, 2) void mma_gemm2(
    const __nv_bfloat16* __restrict__ Ah, const __nv_bfloat16* __restrict__ Al,
    const __nv_bfloat16* __restrict__ Wh, const __nv_bfloat16* __restrict__ Wl,
    const float* __restrict__ bias, float* __restrict__ out,
    int M, int N, int K, int epi)
{
    extern __shared__ char smem[];
    uint32_t sbase = smem_u32(smem);
    int tid = threadIdx.x;
    int wid = tid >> 5, lid = tid & 31;
    int wm = wid & 3, wn = wid >> 2;
    int m0 = blockIdx.y * 128, n0 = blockIdx.x * 128;

    float acc[2][8][4];
#pragma unroll
    for (int mt = 0; mt < 2; mt++)
#pragma unroll
        for (int nt = 0; nt < 8; nt++)
#pragma unroll
            for (int c = 0; c < 4; c++) acc[mt][nt][c] = 0.f;

    const int S = K >> 5;

    auto issue = [&](int s, int buf) {
        uint32_t sb = sbase + (uint32_t)buf * BUFB;
#pragma unroll
        for (int i = 0; i < 2; i++) {
            int ca = tid + i * 256;                  // 0..511
            int row = ca >> 2, sub = ca & 3;
            int ks = sub >> 1, hf = sub & 1;
            size_t go = (size_t)(m0 + row) * K + s * 32 + ks * 16 + hf * 8;
            uint32_t sp = sb + ks * 6144 + row * 48 + hf * 16;
            CP16(sp, Ah + go);
            CP16(sp + 12288, Al + go);
        }
#pragma unroll
        for (int i = 0; i < 2; i++) {
            int cb = tid + i * 256;
            int krow = cb >> 4, nc = cb & 15;
            size_t go = (size_t)(s * 32 + krow) * N + n0 + nc * 8;
            uint32_t sp = sb + OFF_BH + (krow >> 4) * 4352 + (krow & 15) * 272 + nc * 16;
            CP16(sp, Wh + go);
            CP16(sp + 8704, Wl + go);
        }
    };

    issue(0, 0); CP_COMMIT();
    if (S > 1) issue(1, 1);
    CP_COMMIT();

    const int lr = lid & 7, q1 = (lid >> 3) & 1, q2 = lid >> 4;

    for (int s = 0; s < S; s++) {
        int buf = s & 1;
        CP_WAIT1();
        __syncthreads();
        uint32_t sb = sbase + (uint32_t)buf * BUFB;
#pragma unroll
        for (int ks = 0; ks < 2; ks++) {
            uint32_t ah[2][4], al[2][4];
#pragma unroll
            for (int mt = 0; mt < 2; mt++) {
                int mrow = wm * 32 + mt * 16 + lr + q1 * 8;
                uint32_t aoff = sb + ks * 6144 + mrow * 48 + q2 * 16;
                ldsm4(ah[mt], aoff);
                ldsm4(al[mt], aoff + 12288);
            }
#pragma unroll
            for (int nt = 0; nt < 4; nt++) {
                int nb = wn * 64 + nt * 16;
                uint32_t boff = sb + OFF_BH + ks * 4352 + (lr + q1 * 8) * 272
                              + (nb + q2 * 8) * 2;
                uint32_t bh[4], bl[4];
                ldsm4t(bh, boff);
                ldsm4t(bl, boff + 8704);
#pragma unroll
                for (int mt = 0; mt < 2; mt++) {
                    mma16816(acc[mt][nt * 2 + 0], ah[mt], bh);
                    mma16816(acc[mt][nt * 2 + 0], ah[mt], bl);
                    mma16816(acc[mt][nt * 2 + 0], al[mt], bh);
                    mma16816(acc[mt][nt * 2 + 1], ah[mt], bh + 2);
                    mma16816(acc[mt][nt * 2 + 1], ah[mt], bl + 2);
                    mma16816(acc[mt][nt * 2 + 1], al[mt], bh + 2);
                }
            }
        }
        __syncthreads();
        if (s + 2 < S) issue(s + 2, buf);
        CP_COMMIT();
    }

    // ---- epilogue ----
    int g = lid >> 2, tg = lid & 3;
    if (epi <= 1) {
#pragma unroll
        for (int mt = 0; mt < 2; mt++) {
            int r0 = m0 + wm * 32 + mt * 16 + g;
            int r1 = r0 + 8;
#pragma unroll
            for (int nt = 0; nt < 8; nt++) {
                int col = n0 + wn * 64 + nt * 8 + tg * 2;
                float b0 = bias[col], b1 = bias[col + 1];
                float v00 = acc[mt][nt][0] + b0, v01 = acc[mt][nt][1] + b1;
                float v10 = acc[mt][nt][2] + b0, v11 = acc[mt][nt][3] + b1;
                if (epi == 1) {
                    v00 = silu_f(v00); v01 = silu_f(v01);
                    v10 = silu_f(v10); v11 = silu_f(v11);
                }
                *(float2*)(out + (size_t)r0 * N + col) = make_float2(v00, v01);
                *(float2*)(out + (size_t)r1 * N + col) = make_float2(v10, v11);
            }
        }
    } else {
        // transposed store via smem: ts[col][m], stride 132 floats
        float* ts = (float*)smem;
#pragma unroll
        for (int mt = 0; mt < 2; mt++) {
            int rl0 = wm * 32 + mt * 16 + g;
            int rl1 = rl0 + 8;
            int r0 = m0 + rl0, r1 = m0 + rl1;
            float dec0 = 1.f, dec1 = 1.f;
            if (epi == 3) {
                int a = r0 >> 6, b = r0 & 63;
                float adi = (a < 32) ? (float)a : (float)(64 - a);
                float adj = (b < 32) ? (float)b : (float)(64 - b);
                dec0 = __expf(-1.00050033e-3f * (adi + adj));
                a = r1 >> 6; b = r1 & 63;
                adi = (a < 32) ? (float)a : (float)(64 - a);
                adj = (b < 32) ? (float)b : (float)(64 - b);
                dec1 = __expf(-1.00050033e-3f * (adi + adj));
            }
#pragma unroll
            for (int nt = 0; nt < 8; nt++) {
                int cl = wn * 64 + nt * 8 + tg * 2;
                float b0 = bias[n0 + cl], b1 = bias[n0 + cl + 1];
                float v00 = acc[mt][nt][0] + b0, v01 = acc[mt][nt][1] + b1;
                float v10 = acc[mt][nt][2] + b0, v11 = acc[mt][nt][3] + b1;
                if (epi == 2) {
                    v00 = silu_f(v00); v01 = silu_f(v01);
                    v10 = silu_f(v10); v11 = silu_f(v11);
                } else {
                    v00 *= dec0; v01 *= dec0; v10 *= dec1; v11 *= dec1;
                }
                ts[cl * 132 + rl0]       = v00;
                ts[(cl + 1) * 132 + rl0] = v01;
                ts[cl * 132 + rl1]       = v10;
                ts[(cl + 1) * 132 + rl1] = v11;
            }
        }
        __syncthreads();
        int col = tid >> 1, mh = tid & 1;
        const float* src = ts + col * 132 + mh * 64;
        float* dst = out + (size_t)(n0 + col) * M + m0 + mh * 64;
#pragma unroll
        for (int i = 0; i < 16; i++)
            ((float4*)dst)[i] = ((const float4*)src)[i];
    }
}

// ---- fp32 -> split bf16 ----
__global__ void cvt_split(const float* __restrict__ in,
                          __nv_bfloat16* __restrict__ hi, __nv_bfloat16* __restrict__ lo,
                          int n4)
{
    int i = blockIdx.x * blockDim.x + threadIdx.x;
    if (i < n4) {
        float4 v = ((const float4*)in)[i];
        float f[4] = {v.x, v.y, v.z, v.w};
        __nv_bfloat16 h[4], l[4];
#pragma unroll
        for (int t = 0; t < 4; t++) {
            h[t] = __float2bfloat16(f[t]);
            l[t] = __float2bfloat16(f[t] - __bfloat162float(h[t]));
        }
        ((uint2*)hi)[i] = *(uint2*)h;
        ((uint2*)lo)[i] = *(uint2*)l;
    }
}

// ---- RPE position MLP ----
__global__ __launch_bounds__(64) void rpe_mlp_kernel(
    const float* __restrict__ pos_w, const float* __restrict__ pos_b,
    const float* __restrict__ lw, const float* __restrict__ lb,
    float* __restrict__ T)
{
    __shared__ float sx[64];
    __shared__ float st[64];
    int p = blockIdx.x;
    int tid = threadIdx.x;
    int a = p >> 6, b = p & 63;
    float di = (a < 32) ? (float)a : (float)(a - 64);
    float dj = (b < 32) ? (float)b : (float)(b - 64);
    float x = di * pos_w[tid] + dj * pos_w[64 + tid] + pos_b[tid];

    for (int l = 0; l < 3; l++) {
        sx[tid] = x;
        __syncthreads();
        float ss = 0.f;
#pragma unroll 8
        for (int k = 0; k < 64; k++) ss += sx[k] * sx[k];
        float rms = sqrtf(ss * (1.0f / 64.0f));
        float t = silu_f(x / (rms + 1e-8f));
        st[tid] = t;
        __syncthreads();
        float y = lb[l * 64 + tid];
#pragma unroll 8
        for (int k = 0; k < 64; k++) y += st[k] * lw[l * 4096 + k * 64 + tid];
        x = y;
        __syncthreads();
    }
    sx[tid] = x;
    __syncthreads();
    float ss = 0.f;
#pragma unroll 8
    for (int k = 0; k < 64; k++) ss += sx[k] * sx[k];
    float rms = sqrtf(ss * (1.0f / 64.0f));
    T[p * 64 + tid] = silu_f(x / (rms + 1e-8f));
}

// ---- Toeplitz token mixing ----
__global__ __launch_bounds__(256) void conv_toeplitz(
    const float* __restrict__ coef, const float* __restrict__ vt, float* __restrict__ ot)
{
    __shared__ float sc[4096];
    __shared__ float sv[8192];
    int c = blockIdx.x;
    int bg = blockIdx.y;
    int tid = threadIdx.x;

    const float* cp = coef + (size_t)c * 4096;
    const float* vp = vt + (size_t)c * MTOT + (size_t)bg * 8 * 1024;
    for (int i = tid; i < 4096; i += 256) sc[i] = cp[i];
    for (int i = tid; i < 8192; i += 256) sv[i] = vp[i];
    __syncthreads();

    float acc[4][8];
#pragma unroll
    for (int t = 0; t < 4; t++)
#pragma unroll
        for (int bb = 0; bb < 8; bb++) acc[t][bb] = 0.f;

    int i0 = tid >> 5;
    int j = tid & 31;

    for (int p = 0; p < 32; p++) {
        int ro[4];
#pragma unroll
        for (int t = 0; t < 4; t++) ro[t] = ((i0 + 8 * t - p) & 63) << 6;
        int base = p << 5;
#pragma unroll 4
        for (int q = 0; q < 32; q++) {
            int co = (j - q) & 63;
            float cf0 = sc[ro[0] + co];
            float cf1 = sc[ro[1] + co];
            float cf2 = sc[ro[2] + co];
            float cf3 = sc[ro[3] + co];
#pragma unroll
            for (int bb = 0; bb < 8; bb++) {
                float vv = sv[bb * 1024 + base + q];
                acc[0][bb] += cf0 * vv;
                acc[1][bb] += cf1 * vv;
                acc[2][bb] += cf2 * vv;
                acc[3][bb] += cf3 * vv;
            }
        }
    }

    float* op = ot + (size_t)c * MTOT + (size_t)bg * 8 * 1024;
#pragma unroll
    for (int t = 0; t < 4; t++)
#pragma unroll
        for (int bb = 0; bb < 8; bb++)
            op[bb * 1024 + t * 256 + tid] = acc[t][bb];
}

// ---- gate: emits split-bf16 g directly ----
__global__ void gate_mul(const float* __restrict__ u, const float* __restrict__ ot,
                         __nv_bfloat16* __restrict__ gh, __nv_bfloat16* __restrict__ gl)
{
    __shared__ float sm[32][33];
    int c0 = blockIdx.x * 32;
    int r0 = blockIdx.y * 32;
    int tx = threadIdx.x, ty = threadIdx.y;
    sm[ty][tx] = ot[(size_t)(c0 + ty) * MTOT + r0 + tx];
    __syncthreads();
    size_t idx = (size_t)(r0 + ty) * D1X + c0 + tx;
    float gv = u[idx] * sm[tx][ty];
    __nv_bfloat16 h = __float2bfloat16(gv);
    gh[idx] = h;
    gl[idx] = __float2bfloat16(gv - __bfloat162float(h));
}

// ---- x1 = x + o_proj; emits fp32 + split-bf16 ----
__global__ void ew_add_split(const float* __restrict__ a, const float* __restrict__ b,
                             float* __restrict__ o,
                             __nv_bfloat16* __restrict__ oh, __nv_bfloat16* __restrict__ ol,
                             int n4)
{
    int i = blockIdx.x * blockDim.x + threadIdx.x;
    if (i < n4) {
        float4 x = ((const float4*)a)[i];
        float4 y = ((const float4*)b)[i];
        float f[4] = {x.x + y.x, x.y + y.y, x.z + y.z, x.w + y.w};
        ((float4*)o)[i] = make_float4(f[0], f[1], f[2], f[3]);
        __nv_bfloat16 h[4], l[4];
#pragma unroll
        for (int t = 0; t < 4; t++) {
            h[t] = __float2bfloat16(f[t]);
            l[t] = __float2bfloat16(f[t] - __bfloat162float(h[t]));
        }
        ((uint2*)oh)[i] = *(uint2*)h;
        ((uint2*)ol)[i] = *(uint2*)l;
    }
}

// ---- h2 = h1 * h2; emits split-bf16 only ----
__global__ void ew_mul_split(const float* __restrict__ a, const float* __restrict__ b,
                             __nv_bfloat16* __restrict__ oh, __nv_bfloat16* __restrict__ ol,
                             int n4)
{
    int i = blockIdx.x * blockDim.x + threadIdx.x;
    if (i < n4) {
        float4 x = ((const float4*)a)[i];
        float4 y = ((const float4*)b)[i];
        float f[4] = {x.x * y.x, x.y * y.y, x.z * y.z, x.w * y.w};
        __nv_bfloat16 h[4], l[4];
#pragma unroll
        for (int t = 0; t < 4; t++) {
            h[t] = __float2bfloat16(f[t]);
            l[t] = __float2bfloat16(f[t] - __bfloat162float(h[t]));
        }
        ((uint2*)oh)[i] = *(uint2*)h;
        ((uint2*)ol)[i] = *(uint2*)l;
    }
}

__global__ __launch_bounds__(128) void final_srms(
    const float* __restrict__ x1, const float* __restrict__ mlp, float* __restrict__ out)
{
    __shared__ float sred[4];
    int row = blockIdx.x;
    int tid = threadIdx.x;
    const float* mp = mlp + (size_t)row * DIMX;
    float v[4];
    float ss = 0.f;
#pragma unroll
    for (int t = 0; t < 4; t++) { v[t] = mp[tid + t * 128]; ss += v[t] * v[t]; }
#pragma unroll
    for (int o = 16; o > 0; o >>= 1) ss += __shfl_xor_sync(0xffffffffu, ss, o);
    if ((tid & 31) == 0) sred[tid >> 5] = ss;
    __syncthreads();
    float tot = sred[0] + sred[1] + sred[2] + sred[3];
    float rms = sqrtf(tot * (1.0f / 512.0f));
    float inv = 1.0f / (rms + 1e-8f);
    const float* xp = x1 + (size_t)row * DIMX;
    float* op = out + (size_t)row * DIMX;
#pragma unroll
    for (int t = 0; t < 4; t++) op[tid + t * 128] = xp[tid + t * 128] + v[t] * inv;
}

#define GETSYM(v, s) cudaGetSymbolAddress((void**)&v, s)
#define CVT(src, h, l, n) cvt_split<<<((n)/4 + 255)/256, 256>>>(src, h, l, (n)/4)

extern "C" void kernel_launch(void* const* d_in, const int* in_sizes, int n_in,
                              void* d_out, int out_size)
{
    (void)in_sizes; (void)n_in; (void)out_size;
    const float* x      = (const float*)d_in[0];
    const float* u_w    = (const float*)d_in[1];
    const float* u_b    = (const float*)d_in[2];
    const float* v_w    = (const float*)d_in[3];
    const float* v_b    = (const float*)d_in[4];
    const float* o_w    = (const float*)d_in[5];
    const float* o_b    = (const float*)d_in[6];
    const float* pos_w  = (const float*)d_in[7];
    const float* pos_b  = (const float*)d_in[8];
    const float* rpe_lw = (const float*)d_in[9];
    const float* rpe_lb = (const float*)d_in[10];
    const float* rpe_ow = (const float*)d_in[11];
    const float* rpe_ob = (const float*)d_in[12];
    const float* l1_w   = (const float*)d_in[13];
    const float* l1_b   = (const float*)d_in[14];
    const float* l2_w   = (const float*)d_in[15];
    const float* l2_b   = (const float*)d_in[16];
    const float* l3_w   = (const float*)d_in[17];
    const float* l3_b   = (const float*)d_in[18];
    float* out = (float*)d_out;

    float *T, *coef, *u, *vt, *ot, *x1, *h1, *h2, *mlp;
    GETSYM(T, g_T); GETSYM(coef, g_coef); GETSYM(u, g_u); GETSYM(vt, g_vt);
    GETSYM(ot, g_ot); GETSYM(x1, g_x1); GETSYM(h1, g_h1); GETSYM(h2, g_h2);
    GETSYM(mlp, g_mlp);

    __nv_bfloat16 *xh, *xl, *Th, *Tl, *uwh, *uwl, *vwh, *vwl, *owh, *owl;
    __nv_bfloat16 *l1h, *l1l, *l2h, *l2l, *l3h, *l3l, *rwh, *rwl;
    __nv_bfloat16 *gh, *gl, *x1h, *x1l, *h2h, *h2l;
    GETSYM(xh, b_xh); GETSYM(xl, b_xl); GETSYM(Th, b_Th); GETSYM(Tl, b_Tl);
    GETSYM(uwh, b_uwh); GETSYM(uwl, b_uwl); GETSYM(vwh, b_vwh); GETSYM(vwl, b_vwl);
    GETSYM(owh, b_owh); GETSYM(owl, b_owl);
    GETSYM(l1h, b_l1h); GETSYM(l1l, b_l1l); GETSYM(l2h, b_l2h); GETSYM(l2l, b_l2l);
    GETSYM(l3h, b_l3h); GETSYM(l3l, b_l3l); GETSYM(rwh, b_rwh); GETSYM(rwl, b_rwl);
    GETSYM(gh, b_gh); GETSYM(gl, b_gl); GETSYM(x1h, b_x1h); GETSYM(x1l, b_x1l);
    GETSYM(h2h, b_h2h); GETSYM(h2l, b_h2l);

    cudaFuncSetAttribute(mma_gemm2, cudaFuncAttributeMaxDynamicSharedMemorySize, 2 * BUFB);

    // weight + input conversions
    CVT(x, xh, xl, MTOT * DIMX);
    CVT(u_w, uwh, uwl, DIMX * D1X);
    CVT(v_w, vwh, vwl, DIMX * D1X);
    CVT(o_w, owh, owl, D1X * DIMX);
    CVT(l1_w, l1h, l1l, DIMX * GLUX);
    CVT(l2_w, l2h, l2l, DIMX * GLUX);
    CVT(l3_w, l3h, l3l, GLUX * DIMX);
    CVT(rpe_ow, rwh, rwl, RPED * D1X);

    rpe_mlp_kernel<<<NPOS, 64>>>(pos_w, pos_b, rpe_lw, rpe_lb, T);
    CVT(T, Th, Tl, NPOS * RPED);
    // coef = decay * (T @ rpe_ow + rpe_ob), transposed
    mma_gemm2<<<dim3(D1X/128, NPOS/128), 256, 2*BUFB>>>(Th, Tl, rwh, rwl, rpe_ob, coef,
                                                        NPOS, D1X, RPED, 3);
    // u = silu(x@u_w+b); vt = silu(x@v_w+b)^T
    mma_gemm2<<<dim3(D1X/128, MTOT/128), 256, 2*BUFB>>>(xh, xl, uwh, uwl, u_b, u,
                                                        MTOT, D1X, DIMX, 1);
    mma_gemm2<<<dim3(D1X/128, MTOT/128), 256, 2*BUFB>>>(xh, xl, vwh, vwl, v_b, vt,
                                                        MTOT, D1X, DIMX, 2);
    conv_toeplitz<<<dim3(D1X, 2), 256>>>(coef, vt, ot);
    gate_mul<<<dim3(D1X/32, MTOT/32), dim3(32, 32)>>>(u, ot, gh, gl);
    // x1 = x + (g @ o_w + o_b)
    mma_gemm2<<<dim3(DIMX/128, MTOT/128), 256, 2*BUFB>>>(gh, gl, owh, owl, o_b, mlp,
                                                         MTOT, DIMX, D1X, 0);
    ew_add_split<<<(MTOT*DIMX/4 + 255)/256, 256>>>(x, mlp, x1, x1h, x1l, MTOT*DIMX/4);
    // GLU MLP
    mma_gemm2<<<dim3(GLUX/128, MTOT/128), 256, 2*BUFB>>>(x1h, x1l, l1h, l1l, l1_b, h1,
                                                         MTOT, GLUX, DIMX, 1);
    mma_gemm2<<<dim3(GLUX/128, MTOT/128), 256, 2*BUFB>>>(x1h, x1l, l2h, l2l, l2_b, h2,
                                                         MTOT, GLUX, DIMX, 0);
    ew_mul_split<<<(MTOT*GLUX/4 + 255)/256, 256>>>(h1, h2, h2h, h2l, MTOT*GLUX/4);
    mma_gemm2<<<dim3(DIMX/128, MTOT/128), 256, 2*BUFB>>>(h2h, h2l, l3h, l3l, l3_b, mlp,
                                                         MTOT, DIMX, GLUX, 0);
    final_srms<<<MTOT, 128>>>(x1, mlp, out);
}